// round 15
// baseline (speedup 1.0000x reference)
#include <cuda_runtime.h>
#include <math.h>

// NeuS importance sampling — Round 15: R14 + (a) m = A/D + 1e-7 directly
// (one fewer packed op/pair), (b) zero-init syncwarp hoisted to top (single
// tail sync), (c) 128-thread blocks for finer tail granularity.
// 2 rays/warp, 16 lanes/ray, 4 samples/lane, scalar-LDS gather.

#define WARPS_PER_BLOCK 4
#define NS 64

typedef unsigned long long u64;

__device__ __forceinline__ float ex2(float x){ float r; asm("ex2.approx.ftz.f32 %0, %1;" : "=f"(r) : "f"(x)); return r; }
__device__ __forceinline__ float rcpf(float x){ float r; asm("rcp.approx.ftz.f32 %0, %1;" : "=f"(r) : "f"(x)); return r; }
__device__ __forceinline__ float sqrt_approx(float x){ float r; asm("sqrt.approx.ftz.f32 %0, %1;" : "=f"(r) : "f"(x)); return r; }
__device__ __forceinline__ u64 pk(float lo, float hi){ u64 r; asm("mov.b64 %0, {%1, %2};" : "=l"(r) : "f"(lo), "f"(hi)); return r; }
__device__ __forceinline__ void upk(u64 p, float& lo, float& hi){ asm("mov.b64 {%0, %1}, %2;" : "=f"(lo), "=f"(hi) : "l"(p)); }
__device__ __forceinline__ u64 add2(u64 a, u64 b){ u64 r; asm("add.rn.f32x2 %0, %1, %2;" : "=l"(r) : "l"(a), "l"(b)); return r; }
__device__ __forceinline__ u64 mul2(u64 a, u64 b){ u64 r; asm("mul.rn.f32x2 %0, %1, %2;" : "=l"(r) : "l"(a), "l"(b)); return r; }
__device__ __forceinline__ u64 fmaa2(u64 a, u64 b, u64 c){ u64 r; asm("fma.rn.f32x2 %0, %1, %2, %3;" : "=l"(r) : "l"(a), "l"(b), "l"(c)); return r; }
__device__ __forceinline__ int cvt_rpi(float x){ int r; asm("cvt.rpi.ftz.s32.f32 %0, %1;" : "=r"(r) : "f"(x)); return r; }

__global__ __launch_bounds__(WARPS_PER_BLOCK * 32)
void neus_kernel(const float* __restrict__ rays_o,
                 const float* __restrict__ rays_d,
                 const float* __restrict__ z_vals,
                 const float* __restrict__ sdf,
                 float* __restrict__ out,
                 int n_rays)
{
    const float DZ   = 1.5f / 63.0f;
    const float IDZ  = 42.0f;                        // 1/DZ exact
    const float C1   = 0.5f * DZ / (DZ + 1e-5f);
    const float C2   = -64.0f * 1.4426950408889634f; // -inv_s * log2(e)
    const float C12  = C1 * C2;                      // < 0
    const float HC2  = 0.5f * C2;
    const float ACAP = 60.0f;

    const int wib  = threadIdx.x >> 5;
    const int lane = threadIdx.x & 31;
    const int h    = lane >> 4;          // ray slot in warp
    const int q    = lane & 15;          // sublane in ray
    const int ray  = (blockIdx.x * WARPS_PER_BLOCK + wib) * 2 + h;
    if (ray >= n_rays) return;           // never taken (grid divides exactly)

    __shared__ float sh_c[WARPS_PER_BLOCK][2][NS];
    __shared__ int   sh_m[WARPS_PER_BLOCK][2][NS];
    float* shc = sh_c[wib][h];
    int*   shm = sh_m[wib][h];

    // zero scatter table, then barrier NOW (all lanes arrive together here;
    // covers zeros-before-atomics so the tail needs only one sync)
    reinterpret_cast<int4*>(shm)[q] = make_int4(0, 0, 0, 0);
    __syncwarp();

    const unsigned FULL = 0xffffffffu;
    const size_t base = (size_t)ray * NS;

    const float4 ss = reinterpret_cast<const float4*>(sdf + base)[q];
    const float z0  = z_vals[base];

    // sphere-interval inside test: r(z)<1 ⇔ z ∈ (zl, zr); hull over interval pairs
    const float ox = rays_o[3*ray+0], oy = rays_o[3*ray+1], oz = rays_o[3*ray+2];
    const float dx = rays_d[3*ray+0], dy = rays_d[3*ray+1], dz = rays_d[3*ray+2];
    const float hw = -(ox*dx + oy*dy + oz*dz);               // -(o.d)
    const float o2 = fmaf(ox, ox, fmaf(oy, oy, oz*oz));
    const float sq = sqrt_approx(fmaf(hw, hw, 1.0f - o2));   // NaN if no hit
    const int lo_i = cvt_rpi(fmaf(hw - sq - z0, IDZ, -1.0f));// NaN -> 0
    const int hi_i = cvt_rpi((hw + sq - z0) * IDZ);
    const unsigned wid = (unsigned)(hi_i - lo_i);            // empty if no hit
    const int kb = 4*q;
    const int j0 = kb - lo_i;

    // sdf forward differences
    const float s4 = __shfl_down_sync(FULL, ss.x, 1, 16);
    const float d0 = ss.y - ss.x;
    const float d1 = ss.z - ss.y;
    const float d2 = ss.w - ss.z;
    const float d3 = s4  - ss.w;
    float dprev = __shfl_up_sync(FULL, d3, 1, 16);
    if (q == 0) dprev = 0.0f;

    const float dl[4] = {dprev, d0, d1, d2};
    const float dr[4] = {d0, d1, d2, d3};

    // g = t*C2 >= 0 (t never materialized)
    float g[4];
    #pragma unroll
    for (int i = 0; i < 4; ++i) {
        float gi = fmaxf(fminf(dl[i], dr[i]) * C12, 0.0f);
        const bool inside = (unsigned)(j0 + i) < wid;
        g[i] = inside ? gi : 0.0f;
    }

    // ---- packed sigmoid / m over interval pairs ----
    const u64 ONE2  = pk(1.0f, 1.0f);
    const u64 NEG12 = pk(-1.0f, -1.0f);
    const u64 HC2P  = pk(HC2, HC2);
    const u64 E5P   = pk(1e-5f, 1e-5f);
    const u64 E7P   = pk(1e-7f, 1e-7f);

    float m[4];
    #pragma unroll
    for (int p = 0; p < 2; ++p) {
        const float sLo  = (p == 0) ? ss.x : ss.z;
        const float sMid = (p == 0) ? ss.y : ss.w;
        const float sHi  = (p == 0) ? ss.z : s4;
        const u64 sA   = pk(sLo, sMid);
        const u64 sB   = pk(sMid, sHi);
        const u64 mC2  = mul2(add2(sA, sB), HC2P);   // mid * C2
        const u64 gp   = pk(g[2*p], g[2*p+1]);
        const u64 bArg = add2(mC2, gp);              // (mid + t) * C2
        const u64 aArg = fmaa2(gp, NEG12, mC2);      // (mid - t) * C2
        float aa0, aa1, bb0, bb1;
        upk(aArg, aa0, aa1);
        upk(bArg, bb0, bb1);
        const float a0 = ex2(fminf(aa0, ACAP));
        const float a1 = ex2(fminf(aa1, ACAP));
        const float b0 = ex2(fminf(bb0, ACAP));
        const float b1 = ex2(fminf(bb1, ACAP));
        const u64 A = add2(pk(a0, a1), ONE2);
        const u64 B = add2(pk(b0, b1), ONE2);
        const u64 D = mul2(B, fmaa2(E5P, A, ONE2));
        float df0, df1;
        upk(D, df0, df1);
        const u64 R = pk(rcpf(df0), rcpf(df1));
        // m = (A + 1e-7 D)/D = A/D + 1e-7 exactly -> one packed fma
        upk(fmaa2(A, R, E7P), m[2*p], m[2*p+1]);
    }
    if (q == 15) m[3] = 1.0f;                        // interval 63 doesn't exist

    // ---- fused affine scan: prefix-product of m AND prefix-sum of T ----
    const float pm2 = m[0] * m[1];
    const float pm3 = pm2 * m[2];
    float LP = pm3 * m[3];
    float LS = 1.0f + m[0] + pm2 + pm3;
    #pragma unroll
    for (int off = 1; off < 16; off <<= 1) {
        const float pl = __shfl_up_sync(FULL, LP, off, 16);
        const float sl = __shfl_up_sync(FULL, LS, off, 16);
        if (q >= off) { LS = fmaf(pl, LS, sl); LP *= pl; }
    }
    const float Plast = __shfl_sync(FULL, LP, 15, 16);   // T_63
    const float Slast = __shfl_sync(FULL, LS, 15, 16);   // sum T_0..T_63
    float T0 = __shfl_up_sync(FULL, LP, 1, 16);
    float U0 = __shfl_up_sync(FULL, LS, 1, 16);
    if (q == 0) { T0 = 1.0f; U0 = 0.0f; }
    const float T1 = T0 * m[0];
    const float T2 = T1 * m[1];
    const float T3 = T2 * m[2];
    const float U1 = U0 + T0, U2 = U1 + T1, U3 = U2 + T2;

    // total = (1 - T_63) + 1e-7*sum_{k<63} T_k + 63e-5
    const float total = fmaf(1e-7f, Slast - Plast, 1.0f - Plast) + 63.0f * 1e-5f;
    const float rtot  = rcpf(total);

    // ---- packed cdf assembly: c[k] = ((1-T_k) + 1e-7 U_k + 1e-5 k) * rtot ----
    const float f4q = (float)kb;
    const u64 RT2 = pk(rtot, rtot);
    const u64 C64 = pk(64.0f, 64.0f);
    const u64 NH2 = pk(-0.5f, -0.5f);

    float c[4]; int jb[4];
    #pragma unroll
    for (int p = 0; p < 2; ++p) {
        const u64 Tp = (p == 0) ? pk(T0, T1) : pk(T2, T3);
        const u64 Up = (p == 0) ? pk(U0, U1) : pk(U2, U3);
        const u64 Kp = (p == 0) ? pk(f4q, f4q + 1.0f) : pk(f4q + 2.0f, f4q + 3.0f);
        u64 x = fmaa2(Tp, NEG12, ONE2);
        x = fmaa2(E7P, Up, x);
        x = fmaa2(E5P, Kp, x);
        const u64 cp = mul2(x, RT2);
        const u64 jp = fmaa2(C64, cp, NH2);
        float j_lo, j_hi;
        upk(cp, c[2*p], c[2*p+1]);
        upk(jp, j_lo, j_hi);
        jb[2*p]   = cvt_rpi(j_lo);
        jb[2*p+1] = cvt_rpi(j_hi);
    }

    // scalar CDF table (narrow STS/LDS — wide gathers regress, R10/R11)
    reinterpret_cast<float4*>(shc)[q] = make_float4(c[0], c[1], c[2], c[3]);

    // ---- balanced inverse scatter: GUARDED (guard is the atomic-dedup
    // filter — unguarded same-address pad atomics serialized L1, R13) ----
    if (jb[0] < NS) atomicMax(&shm[jb[0]], kb);
    if (jb[1] < NS) atomicMax(&shm[jb[1]], kb + 1);
    if (jb[2] < NS) atomicMax(&shm[jb[2]], kb + 2);
    if (jb[3] < NS) atomicMax(&shm[jb[3]], kb + 3);
    __syncwarp();          // single tail sync: covers shc STS + atomics

    // ---- inclusive max-scan of M -> idx_j ----
    const int4 Mv = reinterpret_cast<const int4*>(shm)[q];
    int i0 = Mv.x;
    int i1 = max(Mv.y, i0);
    int i2 = max(Mv.z, i1);
    int i3 = max(Mv.w, i2);

    int Smax = i3;
    #pragma unroll
    for (int off = 1; off < 16; off <<= 1) {
        const int v = __shfl_up_sync(FULL, Smax, off, 16);
        if (q >= off) Smax = max(Smax, v);
    }
    int pre = __shfl_up_sync(FULL, Smax, 1, 16);
    if (q == 0) pre = 0;
    i0 = max(i0, pre);
    i1 = max(i1, pre);
    i2 = max(i2, pre);
    i3 = max(i3, pre);

    // ---- interpolate: idx <= 62 always (entry 63 never scattered: jb_63=64) ----
    auto interp = [&](int idx, float u) -> float {
        const float cb = shc[idx];
        const float ca = shc[idx + 1];
        float den = ca - cb;
        if (den < 1e-5f) den = 1.0f;
        const float bb = fmaf((float)idx, DZ, z0);
        return fmaf((u - cb) * rcpf(den), DZ, bb);
    };

    const float u0 = fmaf(f4q, 0.015625f, 0.0078125f);
    float4 r;
    r.x = interp(i0, u0);
    r.y = interp(i1, u0 + 0.015625f);
    r.z = interp(i2, u0 + 0.03125f);
    r.w = interp(i3, u0 + 0.046875f);
    reinterpret_cast<float4*>(out + base)[q] = r;
}

extern "C" void kernel_launch(void* const* d_in, const int* in_sizes, int n_in,
                              void* d_out, int out_size) {
    const float* rays_o = (const float*)d_in[0];
    const float* rays_d = (const float*)d_in[1];
    const float* z_vals = (const float*)d_in[2];
    const float* sdf    = (const float*)d_in[3];
    const int n_rays = in_sizes[0] / 3;
    const int rays_per_block = WARPS_PER_BLOCK * 2;
    const int blocks = (n_rays + rays_per_block - 1) / rays_per_block;
    neus_kernel<<<blocks, WARPS_PER_BLOCK * 32>>>(
        rays_o, rays_d, z_vals, sdf, (float*)d_out, n_rays);
}

// round 16
// speedup vs baseline: 1.4880x; 1.4880x over previous
#include <cuda_runtime.h>
#include <math.h>

// NeuS importance sampling — Round 16: exact R14 structure (25.06us champion:
// 256-thr blocks, 2 rays/warp, 16 lanes/ray, dual-sync) + single safe op cut:
// m = A/D + 1e-7 via one packed fma (algebraically exact vs (A+1e-7D)/D).

#define WARPS_PER_BLOCK 8
#define NS 64

typedef unsigned long long u64;

__device__ __forceinline__ float ex2(float x){ float r; asm("ex2.approx.ftz.f32 %0, %1;" : "=f"(r) : "f"(x)); return r; }
__device__ __forceinline__ float rcpf(float x){ float r; asm("rcp.approx.ftz.f32 %0, %1;" : "=f"(r) : "f"(x)); return r; }
__device__ __forceinline__ float sqrt_approx(float x){ float r; asm("sqrt.approx.ftz.f32 %0, %1;" : "=f"(r) : "f"(x)); return r; }
__device__ __forceinline__ u64 pk(float lo, float hi){ u64 r; asm("mov.b64 %0, {%1, %2};" : "=l"(r) : "f"(lo), "f"(hi)); return r; }
__device__ __forceinline__ void upk(u64 p, float& lo, float& hi){ asm("mov.b64 {%0, %1}, %2;" : "=f"(lo), "=f"(hi) : "l"(p)); }
__device__ __forceinline__ u64 add2(u64 a, u64 b){ u64 r; asm("add.rn.f32x2 %0, %1, %2;" : "=l"(r) : "l"(a), "l"(b)); return r; }
__device__ __forceinline__ u64 mul2(u64 a, u64 b){ u64 r; asm("mul.rn.f32x2 %0, %1, %2;" : "=l"(r) : "l"(a), "l"(b)); return r; }
__device__ __forceinline__ u64 fmaa2(u64 a, u64 b, u64 c){ u64 r; asm("fma.rn.f32x2 %0, %1, %2, %3;" : "=l"(r) : "l"(a), "l"(b), "l"(c)); return r; }
__device__ __forceinline__ int cvt_rpi(float x){ int r; asm("cvt.rpi.ftz.s32.f32 %0, %1;" : "=r"(r) : "f"(x)); return r; }

__global__ __launch_bounds__(WARPS_PER_BLOCK * 32)
void neus_kernel(const float* __restrict__ rays_o,
                 const float* __restrict__ rays_d,
                 const float* __restrict__ z_vals,
                 const float* __restrict__ sdf,
                 float* __restrict__ out,
                 int n_rays)
{
    const float DZ   = 1.5f / 63.0f;
    const float IDZ  = 42.0f;                        // 1/DZ exact
    const float C1   = 0.5f * DZ / (DZ + 1e-5f);
    const float C2   = -64.0f * 1.4426950408889634f; // -inv_s * log2(e)
    const float C12  = C1 * C2;                      // < 0
    const float HC2  = 0.5f * C2;
    const float ACAP = 60.0f;

    const int wib  = threadIdx.x >> 5;
    const int lane = threadIdx.x & 31;
    const int h    = lane >> 4;          // ray slot in warp
    const int q    = lane & 15;          // sublane in ray
    const int ray  = (blockIdx.x * WARPS_PER_BLOCK + wib) * 2 + h;
    if (ray >= n_rays) return;

    __shared__ float sh_c[WARPS_PER_BLOCK][2][NS];
    __shared__ int   sh_m[WARPS_PER_BLOCK][2][NS];
    float* shc = sh_c[wib][h];
    int*   shm = sh_m[wib][h];

    reinterpret_cast<int4*>(shm)[q] = make_int4(0, 0, 0, 0);

    const unsigned FULL = 0xffffffffu;
    const size_t base = (size_t)ray * NS;

    const float4 ss = reinterpret_cast<const float4*>(sdf + base)[q];
    const float z0  = z_vals[base];

    // sphere-interval inside test: r(z)<1 ⇔ z ∈ (zl, zr); hull over interval pairs
    const float ox = rays_o[3*ray+0], oy = rays_o[3*ray+1], oz = rays_o[3*ray+2];
    const float dx = rays_d[3*ray+0], dy = rays_d[3*ray+1], dz = rays_d[3*ray+2];
    const float hw = -(ox*dx + oy*dy + oz*dz);               // -(o.d)
    const float o2 = fmaf(ox, ox, fmaf(oy, oy, oz*oz));
    const float sq = sqrt_approx(fmaf(hw, hw, 1.0f - o2));   // NaN if no hit
    const int lo_i = cvt_rpi(fmaf(hw - sq - z0, IDZ, -1.0f));// NaN -> 0
    const int hi_i = cvt_rpi((hw + sq - z0) * IDZ);
    const unsigned wid = (unsigned)(hi_i - lo_i);            // empty if no hit
    const int kb = 4*q;
    const int j0 = kb - lo_i;

    // sdf forward differences
    const float s4 = __shfl_down_sync(FULL, ss.x, 1, 16);
    const float d0 = ss.y - ss.x;
    const float d1 = ss.z - ss.y;
    const float d2 = ss.w - ss.z;
    const float d3 = s4  - ss.w;
    float dprev = __shfl_up_sync(FULL, d3, 1, 16);
    if (q == 0) dprev = 0.0f;

    const float dl[4] = {dprev, d0, d1, d2};
    const float dr[4] = {d0, d1, d2, d3};

    // g = t*C2 >= 0 (t never materialized)
    float g[4];
    #pragma unroll
    for (int i = 0; i < 4; ++i) {
        float gi = fmaxf(fminf(dl[i], dr[i]) * C12, 0.0f);
        const bool inside = (unsigned)(j0 + i) < wid;
        g[i] = inside ? gi : 0.0f;
    }

    // ---- packed sigmoid / m over interval pairs ----
    const u64 ONE2  = pk(1.0f, 1.0f);
    const u64 NEG12 = pk(-1.0f, -1.0f);
    const u64 HC2P  = pk(HC2, HC2);
    const u64 E5P   = pk(1e-5f, 1e-5f);
    const u64 E7P   = pk(1e-7f, 1e-7f);

    float m[4];
    #pragma unroll
    for (int p = 0; p < 2; ++p) {
        const float sLo  = (p == 0) ? ss.x : ss.z;
        const float sMid = (p == 0) ? ss.y : ss.w;
        const float sHi  = (p == 0) ? ss.z : s4;
        const u64 sA   = pk(sLo, sMid);
        const u64 sB   = pk(sMid, sHi);
        const u64 mC2  = mul2(add2(sA, sB), HC2P);   // mid * C2
        const u64 gp   = pk(g[2*p], g[2*p+1]);
        const u64 bArg = add2(mC2, gp);              // (mid + t) * C2
        const u64 aArg = fmaa2(gp, NEG12, mC2);      // (mid - t) * C2
        float aa0, aa1, bb0, bb1;
        upk(aArg, aa0, aa1);
        upk(bArg, bb0, bb1);
        const float a0 = ex2(fminf(aa0, ACAP));
        const float a1 = ex2(fminf(aa1, ACAP));
        const float b0 = ex2(fminf(bb0, ACAP));
        const float b1 = ex2(fminf(bb1, ACAP));
        const u64 A = add2(pk(a0, a1), ONE2);
        const u64 B = add2(pk(b0, b1), ONE2);
        const u64 D = mul2(B, fmaa2(E5P, A, ONE2));
        float df0, df1;
        upk(D, df0, df1);
        const u64 R = pk(rcpf(df0), rcpf(df1));
        // m = (A + 1e-7 D)/D = A/D + 1e-7 -> single packed fma
        upk(fmaa2(A, R, E7P), m[2*p], m[2*p+1]);
    }
    if (q == 15) m[3] = 1.0f;                        // interval 63 doesn't exist

    // ---- fused affine scan: prefix-product of m AND prefix-sum of T ----
    const float pm2 = m[0] * m[1];
    const float pm3 = pm2 * m[2];
    float LP = pm3 * m[3];
    float LS = 1.0f + m[0] + pm2 + pm3;
    #pragma unroll
    for (int off = 1; off < 16; off <<= 1) {
        const float pl = __shfl_up_sync(FULL, LP, off, 16);
        const float sl = __shfl_up_sync(FULL, LS, off, 16);
        if (q >= off) { LS = fmaf(pl, LS, sl); LP *= pl; }
    }
    const float Plast = __shfl_sync(FULL, LP, 15, 16);   // T_63
    const float Slast = __shfl_sync(FULL, LS, 15, 16);   // sum T_0..T_63
    float T0 = __shfl_up_sync(FULL, LP, 1, 16);
    float U0 = __shfl_up_sync(FULL, LS, 1, 16);
    if (q == 0) { T0 = 1.0f; U0 = 0.0f; }
    const float T1 = T0 * m[0];
    const float T2 = T1 * m[1];
    const float T3 = T2 * m[2];
    const float U1 = U0 + T0, U2 = U1 + T1, U3 = U2 + T2;

    // total = (1 - T_63) + 1e-7*sum_{k<63} T_k + 63e-5
    const float total = fmaf(1e-7f, Slast - Plast, 1.0f - Plast) + 63.0f * 1e-5f;
    const float rtot  = rcpf(total);

    // ---- packed cdf assembly: c[k] = ((1-T_k) + 1e-7 U_k + 1e-5 k) * rtot ----
    const float f4q = (float)kb;
    const u64 RT2 = pk(rtot, rtot);
    const u64 C64 = pk(64.0f, 64.0f);
    const u64 NH2 = pk(-0.5f, -0.5f);

    float c[4]; int jb[4];
    #pragma unroll
    for (int p = 0; p < 2; ++p) {
        const u64 Tp = (p == 0) ? pk(T0, T1) : pk(T2, T3);
        const u64 Up = (p == 0) ? pk(U0, U1) : pk(U2, U3);
        const u64 Kp = (p == 0) ? pk(f4q, f4q + 1.0f) : pk(f4q + 2.0f, f4q + 3.0f);
        u64 x = fmaa2(Tp, NEG12, ONE2);
        x = fmaa2(E7P, Up, x);
        x = fmaa2(E5P, Kp, x);
        const u64 cp = mul2(x, RT2);
        const u64 jp = fmaa2(C64, cp, NH2);
        float j_lo, j_hi;
        upk(cp, c[2*p], c[2*p+1]);
        upk(jp, j_lo, j_hi);
        jb[2*p]   = cvt_rpi(j_lo);
        jb[2*p+1] = cvt_rpi(j_hi);
    }

    // scalar CDF table (narrow STS/LDS — wide gathers regress, R10/R11)
    reinterpret_cast<float4*>(shc)[q] = make_float4(c[0], c[1], c[2], c[3]);
    __syncwarp();                                 // M zeros + cdf visible

    // ---- balanced inverse scatter: GUARDED (guard = atomic-dedup filter, R13) ----
    if (jb[0] < NS) atomicMax(&shm[jb[0]], kb);
    if (jb[1] < NS) atomicMax(&shm[jb[1]], kb + 1);
    if (jb[2] < NS) atomicMax(&shm[jb[2]], kb + 2);
    if (jb[3] < NS) atomicMax(&shm[jb[3]], kb + 3);
    __syncwarp();

    // ---- inclusive max-scan of M -> idx_j ----
    const int4 Mv = reinterpret_cast<const int4*>(shm)[q];
    int i0 = Mv.x;
    int i1 = max(Mv.y, i0);
    int i2 = max(Mv.z, i1);
    int i3 = max(Mv.w, i2);

    int Smax = i3;
    #pragma unroll
    for (int off = 1; off < 16; off <<= 1) {
        const int v = __shfl_up_sync(FULL, Smax, off, 16);
        if (q >= off) Smax = max(Smax, v);
    }
    int pre = __shfl_up_sync(FULL, Smax, 1, 16);
    if (q == 0) pre = 0;
    i0 = max(i0, pre);
    i1 = max(i1, pre);
    i2 = max(i2, pre);
    i3 = max(i3, pre);

    // ---- interpolate: idx <= 62 always (entry 63 never scattered: jb_63=64) ----
    auto interp = [&](int idx, float u) -> float {
        const float cb = shc[idx];
        const float ca = shc[idx + 1];
        float den = ca - cb;
        if (den < 1e-5f) den = 1.0f;
        const float bb = fmaf((float)idx, DZ, z0);
        return fmaf((u - cb) * rcpf(den), DZ, bb);
    };

    const float u0 = fmaf(f4q, 0.015625f, 0.0078125f);
    float4 r;
    r.x = interp(i0, u0);
    r.y = interp(i1, u0 + 0.015625f);
    r.z = interp(i2, u0 + 0.03125f);
    r.w = interp(i3, u0 + 0.046875f);
    reinterpret_cast<float4*>(out + base)[q] = r;
}

extern "C" void kernel_launch(void* const* d_in, const int* in_sizes, int n_in,
                              void* d_out, int out_size) {
    const float* rays_o = (const float*)d_in[0];
    const float* rays_d = (const float*)d_in[1];
    const float* z_vals = (const float*)d_in[2];
    const float* sdf    = (const float*)d_in[3];
    const int n_rays = in_sizes[0] / 3;
    const int rays_per_block = WARPS_PER_BLOCK * 2;
    const int blocks = (n_rays + rays_per_block - 1) / rays_per_block;
    neus_kernel<<<blocks, WARPS_PER_BLOCK * 32>>>(
        rays_o, rays_d, z_vals, sdf, (float*)d_out, n_rays);
}

// round 17
// speedup vs baseline: 1.5051x; 1.0115x over previous
#include <cuda_runtime.h>
#include <math.h>

// NeuS importance sampling — Round 17: R16 math, 512-thread blocks (WPB=16).
// Single change: oe 8 -> 4 CTAs/SM to cut cross-CTA L1tex-queue contention
// (R15 showed oe=16 regressed 50%; testing the inverse direction).
// 2 rays/warp, 16 lanes/ray, 4 samples/lane, scalar-LDS gather.

#define WARPS_PER_BLOCK 16
#define NS 64

typedef unsigned long long u64;

__device__ __forceinline__ float ex2(float x){ float r; asm("ex2.approx.ftz.f32 %0, %1;" : "=f"(r) : "f"(x)); return r; }
__device__ __forceinline__ float rcpf(float x){ float r; asm("rcp.approx.ftz.f32 %0, %1;" : "=f"(r) : "f"(x)); return r; }
__device__ __forceinline__ float sqrt_approx(float x){ float r; asm("sqrt.approx.ftz.f32 %0, %1;" : "=f"(r) : "f"(x)); return r; }
__device__ __forceinline__ u64 pk(float lo, float hi){ u64 r; asm("mov.b64 %0, {%1, %2};" : "=l"(r) : "f"(lo), "f"(hi)); return r; }
__device__ __forceinline__ void upk(u64 p, float& lo, float& hi){ asm("mov.b64 {%0, %1}, %2;" : "=f"(lo), "=f"(hi) : "l"(p)); }
__device__ __forceinline__ u64 add2(u64 a, u64 b){ u64 r; asm("add.rn.f32x2 %0, %1, %2;" : "=l"(r) : "l"(a), "l"(b)); return r; }
__device__ __forceinline__ u64 mul2(u64 a, u64 b){ u64 r; asm("mul.rn.f32x2 %0, %1, %2;" : "=l"(r) : "l"(a), "l"(b)); return r; }
__device__ __forceinline__ u64 fmaa2(u64 a, u64 b, u64 c){ u64 r; asm("fma.rn.f32x2 %0, %1, %2, %3;" : "=l"(r) : "l"(a), "l"(b), "l"(c)); return r; }
__device__ __forceinline__ int cvt_rpi(float x){ int r; asm("cvt.rpi.ftz.s32.f32 %0, %1;" : "=r"(r) : "f"(x)); return r; }

__global__ __launch_bounds__(WARPS_PER_BLOCK * 32)
void neus_kernel(const float* __restrict__ rays_o,
                 const float* __restrict__ rays_d,
                 const float* __restrict__ z_vals,
                 const float* __restrict__ sdf,
                 float* __restrict__ out,
                 int n_rays)
{
    const float DZ   = 1.5f / 63.0f;
    const float IDZ  = 42.0f;                        // 1/DZ exact
    const float C1   = 0.5f * DZ / (DZ + 1e-5f);
    const float C2   = -64.0f * 1.4426950408889634f; // -inv_s * log2(e)
    const float C12  = C1 * C2;                      // < 0
    const float HC2  = 0.5f * C2;
    const float ACAP = 60.0f;

    const int wib  = threadIdx.x >> 5;
    const int lane = threadIdx.x & 31;
    const int h    = lane >> 4;          // ray slot in warp
    const int q    = lane & 15;          // sublane in ray
    const int ray  = (blockIdx.x * WARPS_PER_BLOCK + wib) * 2 + h;
    if (ray >= n_rays) return;

    __shared__ float sh_c[WARPS_PER_BLOCK][2][NS];
    __shared__ int   sh_m[WARPS_PER_BLOCK][2][NS];
    float* shc = sh_c[wib][h];
    int*   shm = sh_m[wib][h];

    reinterpret_cast<int4*>(shm)[q] = make_int4(0, 0, 0, 0);

    const unsigned FULL = 0xffffffffu;
    const size_t base = (size_t)ray * NS;

    const float4 ss = reinterpret_cast<const float4*>(sdf + base)[q];
    const float z0  = z_vals[base];

    // sphere-interval inside test: r(z)<1 ⇔ z ∈ (zl, zr); hull over interval pairs
    const float ox = rays_o[3*ray+0], oy = rays_o[3*ray+1], oz = rays_o[3*ray+2];
    const float dx = rays_d[3*ray+0], dy = rays_d[3*ray+1], dz = rays_d[3*ray+2];
    const float hw = -(ox*dx + oy*dy + oz*dz);               // -(o.d)
    const float o2 = fmaf(ox, ox, fmaf(oy, oy, oz*oz));
    const float sq = sqrt_approx(fmaf(hw, hw, 1.0f - o2));   // NaN if no hit
    const int lo_i = cvt_rpi(fmaf(hw - sq - z0, IDZ, -1.0f));// NaN -> 0
    const int hi_i = cvt_rpi((hw + sq - z0) * IDZ);
    const unsigned wid = (unsigned)(hi_i - lo_i);            // empty if no hit
    const int kb = 4*q;
    const int j0 = kb - lo_i;

    // sdf forward differences
    const float s4 = __shfl_down_sync(FULL, ss.x, 1, 16);
    const float d0 = ss.y - ss.x;
    const float d1 = ss.z - ss.y;
    const float d2 = ss.w - ss.z;
    const float d3 = s4  - ss.w;
    float dprev = __shfl_up_sync(FULL, d3, 1, 16);
    if (q == 0) dprev = 0.0f;

    const float dl[4] = {dprev, d0, d1, d2};
    const float dr[4] = {d0, d1, d2, d3};

    // g = t*C2 >= 0 (t never materialized)
    float g[4];
    #pragma unroll
    for (int i = 0; i < 4; ++i) {
        float gi = fmaxf(fminf(dl[i], dr[i]) * C12, 0.0f);
        const bool inside = (unsigned)(j0 + i) < wid;
        g[i] = inside ? gi : 0.0f;
    }

    // ---- packed sigmoid / m over interval pairs ----
    const u64 ONE2  = pk(1.0f, 1.0f);
    const u64 NEG12 = pk(-1.0f, -1.0f);
    const u64 HC2P  = pk(HC2, HC2);
    const u64 E5P   = pk(1e-5f, 1e-5f);
    const u64 E7P   = pk(1e-7f, 1e-7f);

    float m[4];
    #pragma unroll
    for (int p = 0; p < 2; ++p) {
        const float sLo  = (p == 0) ? ss.x : ss.z;
        const float sMid = (p == 0) ? ss.y : ss.w;
        const float sHi  = (p == 0) ? ss.z : s4;
        const u64 sA   = pk(sLo, sMid);
        const u64 sB   = pk(sMid, sHi);
        const u64 mC2  = mul2(add2(sA, sB), HC2P);   // mid * C2
        const u64 gp   = pk(g[2*p], g[2*p+1]);
        const u64 bArg = add2(mC2, gp);              // (mid + t) * C2
        const u64 aArg = fmaa2(gp, NEG12, mC2);      // (mid - t) * C2
        float aa0, aa1, bb0, bb1;
        upk(aArg, aa0, aa1);
        upk(bArg, bb0, bb1);
        const float a0 = ex2(fminf(aa0, ACAP));
        const float a1 = ex2(fminf(aa1, ACAP));
        const float b0 = ex2(fminf(bb0, ACAP));
        const float b1 = ex2(fminf(bb1, ACAP));
        const u64 A = add2(pk(a0, a1), ONE2);
        const u64 B = add2(pk(b0, b1), ONE2);
        const u64 D = mul2(B, fmaa2(E5P, A, ONE2));
        float df0, df1;
        upk(D, df0, df1);
        const u64 R = pk(rcpf(df0), rcpf(df1));
        // m = (A + 1e-7 D)/D = A/D + 1e-7 -> single packed fma
        upk(fmaa2(A, R, E7P), m[2*p], m[2*p+1]);
    }
    if (q == 15) m[3] = 1.0f;                        // interval 63 doesn't exist

    // ---- fused affine scan: prefix-product of m AND prefix-sum of T ----
    const float pm2 = m[0] * m[1];
    const float pm3 = pm2 * m[2];
    float LP = pm3 * m[3];
    float LS = 1.0f + m[0] + pm2 + pm3;
    #pragma unroll
    for (int off = 1; off < 16; off <<= 1) {
        const float pl = __shfl_up_sync(FULL, LP, off, 16);
        const float sl = __shfl_up_sync(FULL, LS, off, 16);
        if (q >= off) { LS = fmaf(pl, LS, sl); LP *= pl; }
    }
    const float Plast = __shfl_sync(FULL, LP, 15, 16);   // T_63
    const float Slast = __shfl_sync(FULL, LS, 15, 16);   // sum T_0..T_63
    float T0 = __shfl_up_sync(FULL, LP, 1, 16);
    float U0 = __shfl_up_sync(FULL, LS, 1, 16);
    if (q == 0) { T0 = 1.0f; U0 = 0.0f; }
    const float T1 = T0 * m[0];
    const float T2 = T1 * m[1];
    const float T3 = T2 * m[2];
    const float U1 = U0 + T0, U2 = U1 + T1, U3 = U2 + T2;

    // total = (1 - T_63) + 1e-7*sum_{k<63} T_k + 63e-5
    const float total = fmaf(1e-7f, Slast - Plast, 1.0f - Plast) + 63.0f * 1e-5f;
    const float rtot  = rcpf(total);

    // ---- packed cdf assembly: c[k] = ((1-T_k) + 1e-7 U_k + 1e-5 k) * rtot ----
    const float f4q = (float)kb;
    const u64 RT2 = pk(rtot, rtot);
    const u64 C64 = pk(64.0f, 64.0f);
    const u64 NH2 = pk(-0.5f, -0.5f);

    float c[4]; int jb[4];
    #pragma unroll
    for (int p = 0; p < 2; ++p) {
        const u64 Tp = (p == 0) ? pk(T0, T1) : pk(T2, T3);
        const u64 Up = (p == 0) ? pk(U0, U1) : pk(U2, U3);
        const u64 Kp = (p == 0) ? pk(f4q, f4q + 1.0f) : pk(f4q + 2.0f, f4q + 3.0f);
        u64 x = fmaa2(Tp, NEG12, ONE2);
        x = fmaa2(E7P, Up, x);
        x = fmaa2(E5P, Kp, x);
        const u64 cp = mul2(x, RT2);
        const u64 jp = fmaa2(C64, cp, NH2);
        float j_lo, j_hi;
        upk(cp, c[2*p], c[2*p+1]);
        upk(jp, j_lo, j_hi);
        jb[2*p]   = cvt_rpi(j_lo);
        jb[2*p+1] = cvt_rpi(j_hi);
    }

    // scalar CDF table (narrow STS/LDS — wide gathers regress, R10/R11)
    reinterpret_cast<float4*>(shc)[q] = make_float4(c[0], c[1], c[2], c[3]);
    __syncwarp();                                 // M zeros + cdf visible

    // ---- balanced inverse scatter: GUARDED (guard = atomic-dedup filter, R13) ----
    if (jb[0] < NS) atomicMax(&shm[jb[0]], kb);
    if (jb[1] < NS) atomicMax(&shm[jb[1]], kb + 1);
    if (jb[2] < NS) atomicMax(&shm[jb[2]], kb + 2);
    if (jb[3] < NS) atomicMax(&shm[jb[3]], kb + 3);
    __syncwarp();

    // ---- inclusive max-scan of M -> idx_j ----
    const int4 Mv = reinterpret_cast<const int4*>(shm)[q];
    int i0 = Mv.x;
    int i1 = max(Mv.y, i0);
    int i2 = max(Mv.z, i1);
    int i3 = max(Mv.w, i2);

    int Smax = i3;
    #pragma unroll
    for (int off = 1; off < 16; off <<= 1) {
        const int v = __shfl_up_sync(FULL, Smax, off, 16);
        if (q >= off) Smax = max(Smax, v);
    }
    int pre = __shfl_up_sync(FULL, Smax, 1, 16);
    if (q == 0) pre = 0;
    i0 = max(i0, pre);
    i1 = max(i1, pre);
    i2 = max(i2, pre);
    i3 = max(i3, pre);

    // ---- interpolate: idx <= 62 always (entry 63 never scattered: jb_63=64) ----
    auto interp = [&](int idx, float u) -> float {
        const float cb = shc[idx];
        const float ca = shc[idx + 1];
        float den = ca - cb;
        if (den < 1e-5f) den = 1.0f;
        const float bb = fmaf((float)idx, DZ, z0);
        return fmaf((u - cb) * rcpf(den), DZ, bb);
    };

    const float u0 = fmaf(f4q, 0.015625f, 0.0078125f);
    float4 r;
    r.x = interp(i0, u0);
    r.y = interp(i1, u0 + 0.015625f);
    r.z = interp(i2, u0 + 0.03125f);
    r.w = interp(i3, u0 + 0.046875f);
    reinterpret_cast<float4*>(out + base)[q] = r;
}

extern "C" void kernel_launch(void* const* d_in, const int* in_sizes, int n_in,
                              void* d_out, int out_size) {
    const float* rays_o = (const float*)d_in[0];
    const float* rays_d = (const float*)d_in[1];
    const float* z_vals = (const float*)d_in[2];
    const float* sdf    = (const float*)d_in[3];
    const int n_rays = in_sizes[0] / 3;
    const int rays_per_block = WARPS_PER_BLOCK * 2;
    const int blocks = (n_rays + rays_per_block - 1) / rays_per_block;
    neus_kernel<<<blocks, WARPS_PER_BLOCK * 32>>>(
        rays_o, rays_d, z_vals, sdf, (float*)d_out, n_rays);
}